// round 9
// baseline (speedup 1.0000x reference)
#include <cuda_runtime.h>
#include <cuda_bf16.h>
#include <math.h>
#include <stdint.h>

#define TT 512
#define DD 512
#define LOG2E 1.4426950408889634f

// ---------------------------------------------------------------------------
// Device-global scratch
// ---------------------------------------------------------------------------
__device__ float g_qkv[3 * DD * TT];                     // [w][o][t] fp32
__device__ __align__(16) __nv_bfloat16 g_aohi[DD * TT];  // ao hi, [d][t]
__device__ __align__(16) __nv_bfloat16 g_aolo[DD * TT];  // ao lo residual
__device__ __align__(16) __nv_bfloat16 gAhi[1536 * 512]; // Wq,Wk,Wv stacked hi
__device__ __align__(16) __nv_bfloat16 gAlo[1536 * 512];
__device__ __align__(16) __nv_bfloat16 gBhi[512 * 512];  // x [t][k]
__device__ __align__(16) __nv_bfloat16 gBlo[512 * 512];
__device__ __align__(16) __nv_bfloat16 gWohi[512 * 512]; // Wo [o][d]
__device__ __align__(16) __nv_bfloat16 gWolo[512 * 512];

__device__ __forceinline__ uint32_t smem_u32(const void* p) {
    uint32_t a;
    asm("{ .reg .u64 t; cvta.to.shared.u64 t, %1; cvt.u32.u64 %0, t; }"
        : "=r"(a) : "l"(p));
    return a;
}
__device__ __forceinline__ void cp16(uint32_t dst, const void* src) {
    asm volatile("cp.async.ca.shared.global [%0], [%1], 16;"
                 :: "r"(dst), "l"(src) : "memory");
}
__device__ __forceinline__ float fast_ex2(float x) {
    float r;
    asm("ex2.approx.ftz.f32 %0, %1;" : "=f"(r) : "f"(x));
    return r;
}

#define MMA16816(c, a, b) \
    asm volatile( \
        "mma.sync.aligned.m16n8k16.row.col.f32.bf16.bf16.f32 " \
        "{%0,%1,%2,%3},{%4,%5,%6,%7},{%8,%9},{%0,%1,%2,%3};" \
        : "+f"((c)[0]), "+f"((c)[1]), "+f"((c)[2]), "+f"((c)[3]) \
        : "r"((a)[0]), "r"((a)[1]), "r"((a)[2]), "r"((a)[3]), \
          "r"((b)[0]), "r"((b)[1]))

#define LDMX4(r, a) \
    asm volatile( \
        "ldmatrix.sync.aligned.m8n8.x4.shared.b16 {%0,%1,%2,%3}, [%4];" \
        : "=r"((r)[0]), "=r"((r)[1]), "=r"((r)[2]), "=r"((r)[3]) : "r"(a))

#define LDMX4T(r, a) \
    asm volatile( \
        "ldmatrix.sync.aligned.m8n8.x4.trans.shared.b16 {%0,%1,%2,%3}, [%4];" \
        : "=r"((r)[0]), "=r"((r)[1]), "=r"((r)[2]), "=r"((r)[3]) : "r"(a))

// ---------------------------------------------------------------------------
// Split kernel: fp32 -> bf16 hi + bf16 lo(residual), MLP=4.
// Segments (65536 f4 each): 0=Wq 1=Wk 2=Wv -> gA*; 3=x -> gB*; 4=Wo.
// ---------------------------------------------------------------------------
__global__ void __launch_bounds__(256) split_kernel(
        const float4* __restrict__ x,  const float4* __restrict__ Wq,
        const float4* __restrict__ Wk, const float4* __restrict__ Wv,
        const float4* __restrict__ Wo) {
    const int gid = blockIdx.x * 256 + threadIdx.x;   // 0..81919
    const int seg = gid >> 14;
    const int base = (gid & 16383) * 4;

    const float4* src;
    __nv_bfloat16 *dh, *dl;
    switch (seg) {
        case 0: src = Wq; dh = gAhi;          dl = gAlo;          break;
        case 1: src = Wk; dh = gAhi + 262144; dl = gAlo + 262144; break;
        case 2: src = Wv; dh = gAhi + 524288; dl = gAlo + 524288; break;
        case 3: src = x;  dh = gBhi;          dl = gBlo;          break;
        default: src = Wo; dh = gWohi;         dl = gWolo;         break;
    }
    float4 v[4];
#pragma unroll
    for (int i = 0; i < 4; i++) v[i] = src[base + i];
    __nv_bfloat162* oh = (__nv_bfloat162*)dh;
    __nv_bfloat162* ol = (__nv_bfloat162*)dl;
#pragma unroll
    for (int i = 0; i < 4; i++) {
        __nv_bfloat162 h0 = __float22bfloat162_rn(make_float2(v[i].x, v[i].y));
        __nv_bfloat162 h1 = __float22bfloat162_rn(make_float2(v[i].z, v[i].w));
        __nv_bfloat162 l0 = __float22bfloat162_rn(make_float2(
            v[i].x - __bfloat162float(h0.x), v[i].y - __bfloat162float(h0.y)));
        __nv_bfloat162 l1 = __float22bfloat162_rn(make_float2(
            v[i].z - __bfloat162float(h1.x), v[i].w - __bfloat162float(h1.y)));
        oh[(base + i) * 2]     = h0;
        oh[(base + i) * 2 + 1] = h1;
        ol[(base + i) * 2]     = l0;
        ol[(base + i) * 2 + 1] = l1;
    }
}

// ---------------------------------------------------------------------------
// GEMM core: C[(m0+r)*512 + n0+c] (+)= sum_k A[r][k]*B[c][k]
// CTA tile 32(m) x 64(n), 256 threads (8 warps, warp tile 16x16).
// 3-stage cp.async pipeline; 3-pass hi/lo MMA; optional atomic epilogue.
// ATRANS=false: A bf16 [m][k] rows 144B;  ATRANS=true: A bf16 [k][m] rows 80B.
// ---------------------------------------------------------------------------
#define B_MAT 9216                        // 64 rows * 144B
#define CHUNK_MAX 28672                   // ATRANS chunk (largest)
#define GEMM_SMEM (3 * CHUNK_MAX)         // 86016 B

template <bool ATRANS, bool ATOMIC>
__device__ __forceinline__ void gemm_core(
        const uint4* __restrict__ AH, const uint4* __restrict__ AL,
        const uint4* __restrict__ BH, const uint4* __restrict__ BL,
        float* __restrict__ C, int kc0, int nch) {
    extern __shared__ char smem[];
    const uint32_t s0 = smem_u32(smem);

    constexpr int AROWB = ATRANS ? 80 : 144;
    constexpr int A_MAT = ATRANS ? 64 * 80 : 32 * 144;
    constexpr int CHUNK = 2 * A_MAT + 2 * B_MAT;

    const int tid = threadIdx.x;       // 0..255
    const int wid = tid >> 5, lane = tid & 31;
    const int g = lane >> 2, t4 = lane & 3;
    const int wm = (wid & 1) * 16;     // warp m offset
    const int wn = (wid >> 1) * 16;    // warp n offset (4 groups)
    const int m0 = blockIdx.x * 32, n0 = blockIdx.y * 64;

    // ldmatrix lane addressing (verified rounds 7-8)
    const int arow  = lane & 15;
    const int aksel = (lane >> 4) * 16;
    const int brow  = ((lane >> 4) & 1) * 8 + (lane & 7);
    const int bksel = ((lane >> 3) & 1) * 16;
    const int laneRow  = ((lane >> 4) & 1) * 8 + (lane & 7);
    const int laneMsel = ((lane >> 3) & 1) * 8;

    float acc[2][4] = {};

    auto load_chunk = [&](int kc, int st) {
        const uint32_t base = s0 + st * CHUNK;
        // A: 256 uint4 per matrix (hi and lo), 1 per thread each
        {
            size_t ga;
            uint32_t so;
            if (ATRANS) {
                const int row = tid >> 2, c16 = tid & 3;   // 64 rows x 4
                so = row * AROWB + c16 * 16;
                ga = (size_t)(kc * 64 + row) * 64 + (m0 >> 3) + c16;
            } else {
                const int row = tid >> 3, c16 = tid & 7;   // 32 rows x 8
                so = row * AROWB + c16 * 16;
                ga = (size_t)(m0 + row) * 64 + kc * 8 + c16;
            }
            cp16(base + so,         AH + ga);
            cp16(base + A_MAT + so, AL + ga);
        }
        // B: 512 uint4 per matrix, 2 per thread each
#pragma unroll
        for (int it = 0; it < 2; it++) {
            const int idx = it * 256 + tid;
            const int row = idx >> 3, c16 = idx & 7;
            const uint32_t so = row * 144 + c16 * 16;
            const size_t gb = (size_t)(n0 + row) * 64 + kc * 8 + c16;
            cp16(base + 2 * A_MAT + so,         BH + gb);
            cp16(base + 2 * A_MAT + B_MAT + so, BL + gb);
        }
        asm volatile("cp.async.commit_group;" ::: "memory");
    };

    load_chunk(kc0 + 0, 0);
    load_chunk(kc0 + 1, 1);

    for (int c = 0; c < nch; c++) {
        if (c + 2 < nch) {
            load_chunk(kc0 + c + 2, (c + 2) % 3);
            asm volatile("cp.async.wait_group 2;" ::: "memory");
        } else if (c + 1 < nch) {
            asm volatile("cp.async.wait_group 1;" ::: "memory");
        } else {
            asm volatile("cp.async.wait_group 0;" ::: "memory");
        }
        __syncthreads();

        const uint32_t sb = s0 + (c % 3) * CHUNK;
#pragma unroll
        for (int ks = 0; ks < 4; ks++) {
            const int kO = ks * 32;
            uint32_t ah[4], al[4], bh[4], bl[4];
            if (ATRANS) {
                const uint32_t ad = sb + (ks * 16 + laneRow) * AROWB
                                  + (wm + laneMsel) * 2;
                LDMX4T(ah, ad);
                LDMX4T(al, ad + A_MAT);
            } else {
                const uint32_t ad = sb + (wm + arow) * AROWB + kO + aksel;
                LDMX4(ah, ad);
                LDMX4(al, ad + A_MAT);
            }
            {
                const uint32_t bd = sb + 2 * A_MAT + (wn + brow) * 144
                                  + kO + bksel;
                LDMX4(bh, bd);
                LDMX4(bl, bd + B_MAT);
            }
#pragma unroll
            for (int j = 0; j < 2; j++) {
                MMA16816(acc[j], ah, &bh[j * 2]);
                MMA16816(acc[j], ah, &bl[j * 2]);
                MMA16816(acc[j], al, &bh[j * 2]);
            }
        }
        __syncthreads();
    }

    const int r = m0 + wm + g;
#pragma unroll
    for (int j = 0; j < 2; j++) {
        const int col = n0 + wn + j * 8 + 2 * t4;
        if (ATOMIC) {
            atomicAdd(&C[(size_t)r * 512 + col],           acc[j][0]);
            atomicAdd(&C[(size_t)r * 512 + col + 1],       acc[j][1]);
            atomicAdd(&C[(size_t)(r + 8) * 512 + col],     acc[j][2]);
            atomicAdd(&C[(size_t)(r + 8) * 512 + col + 1], acc[j][3]);
        } else {
            *(float2*)&C[(size_t)r * 512 + col] =
                make_float2(acc[j][0], acc[j][1]);
            *(float2*)&C[(size_t)(r + 8) * 512 + col] =
                make_float2(acc[j][2], acc[j][3]);
        }
    }
}

__global__ void __launch_bounds__(256, 2) gemm1_kernel() {
    gemm_core<false, false>((const uint4*)gAhi, (const uint4*)gAlo,
                            (const uint4*)gBhi, (const uint4*)gBlo,
                            g_qkv, 0, 8);
}
__global__ void __launch_bounds__(256, 2) gemm2_kernel(float* __restrict__ y) {
    gemm_core<true, true>((const uint4*)g_aohi, (const uint4*)g_aolo,
                          (const uint4*)gWohi, (const uint4*)gWolo,
                          y, blockIdx.z * 4, 4);
}

// ---------------------------------------------------------------------------
// Attention with fused RoPE; writes bf16 hi/lo split ([d][t]); zeroes y
// for gemm2's atomic epilogue (block c zeroes y row c).
// ---------------------------------------------------------------------------
__global__ void __launch_bounds__(256) attn_kernel(float* __restrict__ y) {
    const int c  = blockIdx.x;
    const int h  = c >> 6;
    const int ch = c & 63;
    const int fi = ch & 31;
    const int pc = ((h < 4) ? (h + 4) : (h - 4)) * 64 + ch;
    const float sgn = (h < 4) ? -1.0f : 1.0f;

    const float* q  = g_qkv + 0 * DD * TT + c  * TT;
    const float* qp = g_qkv + 0 * DD * TT + pc * TT;
    const float* k  = g_qkv + 1 * DD * TT + c  * TT;
    const float* kp = g_qkv + 1 * DD * TT + pc * TT;
    const float* v  = g_qkv + 2 * DD * TT + c  * TT;

    __shared__ float ks[512];
    __shared__ float vs[512];
    __shared__ float cs[512];
    __shared__ float sn[512];
    __shared__ float s_invf;

    const int tid = threadIdx.x;
    // zero y row c (for gemm2 atomic accumulation; runs every replay)
    *(float2*)&y[c * 512 + tid * 2] = make_float2(0.f, 0.f);

    if (tid == 0) s_invf = (float)pow(10000.0, -(double)(2 * fi) / 64.0);
    __syncthreads();
    const float invf = s_invf;

#pragma unroll
    for (int off = 0; off < 512; off += 256) {
        const int tt = tid + off;
        float sv, cv;
        sincosf((float)tt * invf, &sv, &cv);
        cs[tt] = cv;
        sn[tt] = sv;
        ks[tt] = k[tt] * cv + sgn * kp[tt] * sv;
        vs[tt] = v[tt];
    }
    __syncthreads();

#pragma unroll
    for (int rep = 0; rep < 2; rep++) {
        const int i = rep ? (511 - tid) : tid;
        const float qr = q[i] * cs[i] + sgn * qp[i] * sn[i];
        const float qs = qr * (0.125f * LOG2E);
        float l = 0.f, acc = 0.f;
#pragma unroll 4
        for (int j = 0; j <= i; j++) {
            float p = fast_ex2(qs * ks[j]);
            l += p;
            acc += p * vs[j];
        }
        const float o = acc / l;
        const __nv_bfloat16 hb = __float2bfloat16(o);
        g_aohi[c * TT + i] = hb;
        g_aolo[c * TT + i] = __float2bfloat16(o - __bfloat162float(hb));
    }
}

// ---------------------------------------------------------------------------
extern "C" void kernel_launch(void* const* d_in, const int* in_sizes, int n_in,
                              void* d_out, int out_size) {
    const float* x  = (const float*)d_in[0];
    const float* Wq = (const float*)d_in[1];
    const float* Wk = (const float*)d_in[2];
    const float* Wv = (const float*)d_in[3];
    const float* Wo = (const float*)d_in[4];
    float* y = (float*)d_out;

    cudaFuncSetAttribute(gemm1_kernel,
                         cudaFuncAttributeMaxDynamicSharedMemorySize, GEMM_SMEM);
    cudaFuncSetAttribute(gemm2_kernel,
                         cudaFuncAttributeMaxDynamicSharedMemorySize, GEMM_SMEM);

    split_kernel<<<320, 256>>>((const float4*)x, (const float4*)Wq,
                               (const float4*)Wk, (const float4*)Wv,
                               (const float4*)Wo);
    gemm1_kernel<<<dim3(48, 8), 256, GEMM_SMEM>>>();
    attn_kernel<<<512, 256>>>(y);
    gemm2_kernel<<<dim3(16, 8, 2), 256, GEMM_SMEM>>>(y);
}